// round 1
// baseline (speedup 1.0000x reference)
#include <cuda_runtime.h>
#include <math.h>

#define NBAG 512
#define MS 8
#define TT 64
#define BDIM 4096          // NBAG*MS
#define INDIM 360
#define HH 230
#define H2 460
#define G3 690
#define NOUT 53
#define NDOCS 32
#define NENT 8
#define HP 232             // padded H (mult of 8)
#define M_TOT (BDIM * TT)  // 262144

// ------------------- scratch (device globals; no allocs allowed) -------------------
__device__ float g_xg[2ull * M_TOT * G3];       // [dir][m=b*T+t][690]  (x@W_ih^T + b_ih)
__device__ float g_h[2ull * TT * BDIM * HP];    // [dir][t][b][HP] hidden states
__device__ float g_scores[(size_t)BDIM * TT];   // [b][t] word attention logits -> alpha
__device__ float g_wordvec[(size_t)BDIM * H2];  // [b][460]

// =================== 1. input GEMM: xg = bag @ W_ih^T + b_ih (both dirs) ===================
// C[m][n] = sum_k A[m][k]*W[n][k] + b[n];  M=262144, N=690, K=360
// tiles: BM=128, BN=64, BK=8; 256 threads, microtile 8x4
__global__ void input_gemm(const float* __restrict__ A,
                           const float* __restrict__ Wf, const float* __restrict__ bf,
                           const float* __restrict__ Wr, const float* __restrict__ br)
{
    __shared__ float As[8][132];
    __shared__ float Ws[8][68];
    const int dir = blockIdx.z;
    const float* W    = dir ? Wr : Wf;
    const float* bias = dir ? br : bf;
    float* C = g_xg + (size_t)dir * M_TOT * G3;

    const int n0 = blockIdx.x * 64;
    const int m0 = blockIdx.y * 128;
    const int tid = threadIdx.x;
    const int tx = tid & 15, ty = tid >> 4;

    float acc[8][4];
    #pragma unroll
    for (int i = 0; i < 8; i++)
        #pragma unroll
        for (int j = 0; j < 4; j++) acc[i][j] = 0.f;

    const int arow = tid >> 1, ahalf = (tid & 1) * 4;        // A: 128 rows x 8k, float4
    const int wrow = tid >> 2, wk = (tid & 3) * 2;           // W: 64 rows x 8k, float2
    const int wn = n0 + wrow;
    const float* Aptr = A + (size_t)(m0 + arow) * INDIM + ahalf;
    const float* Wptr = (wn < G3) ? (W + (size_t)wn * INDIM + wk) : nullptr;

    for (int k0 = 0; k0 < INDIM; k0 += 8) {
        float4 av = *(const float4*)(Aptr + k0);
        float2 wv = Wptr ? *(const float2*)(Wptr + k0) : make_float2(0.f, 0.f);
        __syncthreads();
        As[ahalf + 0][arow] = av.x;
        As[ahalf + 1][arow] = av.y;
        As[ahalf + 2][arow] = av.z;
        As[ahalf + 3][arow] = av.w;
        Ws[wk + 0][wrow] = wv.x;
        Ws[wk + 1][wrow] = wv.y;
        __syncthreads();
        #pragma unroll
        for (int kk = 0; kk < 8; kk++) {
            float4 w4 = *(float4*)&Ws[kk][tx * 4];
            float4 a0 = *(float4*)&As[kk][ty * 8];
            float4 a1 = *(float4*)&As[kk][ty * 8 + 4];
            float a[8] = {a0.x, a0.y, a0.z, a0.w, a1.x, a1.y, a1.z, a1.w};
            float w[4] = {w4.x, w4.y, w4.z, w4.w};
            #pragma unroll
            for (int i = 0; i < 8; i++)
                #pragma unroll
                for (int j = 0; j < 4; j++) acc[i][j] += a[i] * w[j];
        }
    }

    float bv[4];
    #pragma unroll
    for (int j = 0; j < 4; j++) {
        int n = n0 + tx * 4 + j;
        bv[j] = (n < G3) ? bias[n] : 0.f;
    }
    #pragma unroll
    for (int i = 0; i < 8; i++) {
        size_t row = (size_t)(m0 + ty * 8 + i);
        #pragma unroll
        for (int j = 0; j < 4; j++) {
            int n = n0 + tx * 4 + j;
            if (n < G3) C[row * G3 + n] = acc[i][j] + bv[j];
        }
    }
}

// =================== 2. fused GRU step (both dirs; one launch per step) ===================
// For tile (b,j): 3 dot products h_prev . W_hh[{j, H+j, 2H+j}, :], then gates.
// tiles: BM=64 (b), BN=32 (j), BK=16; 256 threads, 8 rows x 1 col x 3 gates per thread
__global__ void gru_step(const float* __restrict__ Whhf, const float* __restrict__ bhhf,
                         const float* __restrict__ Whhr, const float* __restrict__ bhhr,
                         int s)
{
    __shared__ float Hs[16][65];
    __shared__ float Wg[3][16][33];
    const int dir = blockIdx.z;
    const int t = dir ? (TT - 1 - s) : s;
    const float* W   = dir ? Whhr : Whhf;
    const float* bhh = dir ? bhhr : bhhf;
    const float* xg = g_xg + (size_t)dir * M_TOT * G3;
    float* hslab = g_h + (size_t)dir * TT * BDIM * HP;
    float* hout = hslab + (size_t)t * BDIM * HP;
    const float* hprev = nullptr;
    if (s > 0) hprev = hslab + (size_t)(dir ? (t + 1) : (t - 1)) * BDIM * HP;

    const int b0 = blockIdx.y * 64;
    const int j0 = blockIdx.x * 32;
    const int tid = threadIdx.x;
    const int tx = tid & 31, ty = tid >> 5;

    float ar[8], az[8], an[8];
    #pragma unroll
    for (int i = 0; i < 8; i++) { ar[i] = 0.f; az[i] = 0.f; an[i] = 0.f; }

    const int hrow = tid >> 2, hk = (tid & 3) * 4;   // 64 rows x 16k, 4 scalars/thread
    const int wrow = tid >> 3, wkk = (tid & 7) * 2;  // per gate 32 rows x 16k, 2 scalars
    const int jg = j0 + wrow;

    for (int k0 = 0; k0 < HH; k0 += 16) {
        float hv[4];
        #pragma unroll
        for (int q = 0; q < 4; q++) {
            int k = k0 + hk + q;
            hv[q] = (hprev && k < HH) ? hprev[(size_t)(b0 + hrow) * HP + k] : 0.f;
        }
        float wv[3][2];
        #pragma unroll
        for (int g = 0; g < 3; g++)
            #pragma unroll
            for (int q = 0; q < 2; q++) {
                int k = k0 + wkk + q;
                wv[g][q] = (jg < HH && k < HH) ? W[(size_t)(g * HH + jg) * HH + k] : 0.f;
            }
        __syncthreads();
        #pragma unroll
        for (int q = 0; q < 4; q++) Hs[hk + q][hrow] = hv[q];
        #pragma unroll
        for (int g = 0; g < 3; g++) {
            Wg[g][wkk + 0][wrow] = wv[g][0];
            Wg[g][wkk + 1][wrow] = wv[g][1];
        }
        __syncthreads();
        #pragma unroll
        for (int kk = 0; kk < 16; kk++) {
            float wr = Wg[0][kk][tx], wz = Wg[1][kk][tx], wn = Wg[2][kk][tx];
            #pragma unroll
            for (int i = 0; i < 8; i++) {
                float h = Hs[kk][ty * 8 + i];
                ar[i] += h * wr;
                az[i] += h * wz;
                an[i] += h * wn;
            }
        }
    }

    const int j = j0 + tx;
    if (j < HH) {
        const float brr = bhh[j], bzz = bhh[HH + j], bnn = bhh[2 * HH + j];
        #pragma unroll
        for (int i = 0; i < 8; i++) {
            int b = b0 + ty * 8 + i;
            size_t xb = ((size_t)b * TT + t) * G3;
            float r = 1.f / (1.f + expf(-(xg[xb + j] + ar[i] + brr)));
            float z = 1.f / (1.f + expf(-(xg[xb + HH + j] + az[i] + bzz)));
            float n = tanhf(xg[xb + 2 * HH + j] + r * (an[i] + bnn));
            float hp = hprev ? hprev[(size_t)b * HP + j] : 0.f;
            hout[(size_t)b * HP + j] = (1.f - z) * n + z * hp;
        }
    }
}

// =================== 3. word attention scores ===================
// s[t,b] = sum_j tanh( (out[t,b,:] @ W_word)[j] + b_word[j] ) * proj_word[j]
// out[t,b,k] = k<H ? hf[t,b,k] : hr[t,b,k-H].  GEMM 64 rows x (460 cols in chunks) x K=460.
__global__ void word_score(const float* __restrict__ Ww, const float* __restrict__ bw,
                           const float* __restrict__ pw)
{
    __shared__ float As[16][65];
    __shared__ float Ws2[16][68];
    __shared__ float srow[64];
    const int t = blockIdx.x;
    const int b0 = blockIdx.y * 64;
    const int tid = threadIdx.x;
    const int tx = tid & 15, ty = tid >> 4;
    if (tid < 64) srow[tid] = 0.f;

    const float* h0 = g_h + (size_t)t * BDIM * HP;
    const float* h1 = g_h + (size_t)(TT + t) * BDIM * HP;

    const int arow = tid >> 2, akq = (tid & 3) * 4;  // 64 rows x 16k
    const int wcol = tid & 63, wkq = (tid >> 6) * 4; // 16k x 64 cols

    for (int jc = 0; jc < H2; jc += 64) {
        float acc[4][4];
        #pragma unroll
        for (int i = 0; i < 4; i++)
            #pragma unroll
            for (int j = 0; j < 4; j++) acc[i][j] = 0.f;

        for (int k0 = 0; k0 < H2; k0 += 16) {
            float av[4], wv[4];
            #pragma unroll
            for (int q = 0; q < 4; q++) {
                int k = k0 + akq + q;
                av[q] = (k < HH) ? h0[(size_t)(b0 + arow) * HP + k]
                      : (k < H2) ? h1[(size_t)(b0 + arow) * HP + (k - HH)] : 0.f;
            }
            #pragma unroll
            for (int q = 0; q < 4; q++) {
                int k = k0 + wkq + q;
                int j = jc + wcol;
                wv[q] = (k < H2 && j < H2) ? Ww[(size_t)k * H2 + j] : 0.f;
            }
            __syncthreads();
            #pragma unroll
            for (int q = 0; q < 4; q++) As[akq + q][arow] = av[q];
            #pragma unroll
            for (int q = 0; q < 4; q++) Ws2[wkq + q][wcol] = wv[q];
            __syncthreads();
            #pragma unroll
            for (int kk = 0; kk < 16; kk++) {
                float4 w4 = *(float4*)&Ws2[kk][tx * 4];
                float w[4] = {w4.x, w4.y, w4.z, w4.w};
                float a[4];
                #pragma unroll
                for (int i = 0; i < 4; i++) a[i] = As[kk][ty * 4 + i];
                #pragma unroll
                for (int i = 0; i < 4; i++)
                    #pragma unroll
                    for (int j = 0; j < 4; j++) acc[i][j] += a[i] * w[j];
            }
        }
        float part[4] = {0.f, 0.f, 0.f, 0.f};
        #pragma unroll
        for (int j = 0; j < 4; j++) {
            int col = jc + tx * 4 + j;
            if (col < H2) {
                float bb = bw[col], pp = pw[col];
                #pragma unroll
                for (int i = 0; i < 4; i++) part[i] += tanhf(acc[i][j] + bb) * pp;
            }
        }
        #pragma unroll
        for (int i = 0; i < 4; i++) atomicAdd(&srow[ty * 4 + i], part[i]);
    }
    __syncthreads();
    if (tid < 64) g_scores[(size_t)(b0 + tid) * TT + t] = srow[tid];
}

// =================== 4. softmax over t + weighted sum -> word_vec ===================
__global__ void word_attn()
{
    __shared__ float alpha[TT];
    __shared__ float red[2];
    const int b = blockIdx.x;
    const int tid = threadIdx.x;
    if (tid < TT) alpha[tid] = g_scores[(size_t)b * TT + tid];
    __syncthreads();
    if (tid == 0) {
        float m = -1e30f;
        for (int t2 = 0; t2 < TT; t2++) m = fmaxf(m, alpha[t2]);
        red[0] = m;
    }
    __syncthreads();
    if (tid < TT) alpha[tid] = expf(alpha[tid] - red[0]);
    __syncthreads();
    if (tid == 0) {
        float s = 0.f;
        for (int t2 = 0; t2 < TT; t2++) s += alpha[t2];
        red[1] = 1.f / s;
    }
    __syncthreads();
    if (tid < TT) alpha[tid] *= red[1];
    __syncthreads();
    for (int hcol = tid; hcol < H2; hcol += 256) {
        const float* base = (hcol < HH)
            ? (g_h + (size_t)b * HP + hcol)
            : (g_h + (size_t)TT * BDIM * HP + (size_t)b * HP + (hcol - HH));
        float acc = 0.f;
        #pragma unroll 4
        for (int t2 = 0; t2 < TT; t2++) acc += alpha[t2] * base[(size_t)t2 * BDIM * HP];
        g_wordvec[(size_t)b * H2 + hcol] = acc;
    }
}

// =================== 5. zero output ===================
__global__ void zero_out(float* __restrict__ out, int n)
{
    int i = blockIdx.x * 256 + threadIdx.x;
    if (i < n) out[i] = 0.f;
}

// =================== 6. sentence attention + FC + scatter (one block per bag) ===================
__global__ void sent_kernel(const float* __restrict__ Wsent, const float* __restrict__ bsent,
                            const float* __restrict__ psent, const float* __restrict__ fcW,
                            const float* __restrict__ fcb, const int* __restrict__ pairs,
                            float* __restrict__ out)
{
    __shared__ float wvs[MS][H2];
    __shared__ float score[MS];
    __shared__ float beta[MS];
    __shared__ float sv[H2];
    const int nb = blockIdx.x;
    const int tid = threadIdx.x;

    for (int i = tid; i < MS * H2; i += 256)
        wvs[i / H2][i % H2] = g_wordvec[(size_t)nb * MS * H2 + i];
    if (tid < MS) score[tid] = 0.f;
    __syncthreads();

    for (int j = tid; j < H2; j += 256) {
        float acc[MS];
        #pragma unroll
        for (int s = 0; s < MS; s++) acc[s] = 0.f;
        for (int k = 0; k < H2; k++) {
            float w = Wsent[(size_t)k * H2 + j];
            #pragma unroll
            for (int s = 0; s < MS; s++) acc[s] += wvs[s][k] * w;
        }
        float bb = bsent[j], pp = psent[j];
        #pragma unroll
        for (int s = 0; s < MS; s++) atomicAdd(&score[s], tanhf(acc[s] + bb) * pp);
    }
    __syncthreads();
    if (tid == 0) {
        float m = -1e30f;
        for (int s = 0; s < MS; s++) m = fmaxf(m, score[s]);
        float sum = 0.f;
        for (int s = 0; s < MS; s++) { beta[s] = expf(score[s] - m); sum += beta[s]; }
        float inv = 1.f / sum;
        for (int s = 0; s < MS; s++) beta[s] *= inv;
    }
    __syncthreads();
    for (int hcol = tid; hcol < H2; hcol += 256) {
        float acc = 0.f;
        #pragma unroll
        for (int s = 0; s < MS; s++) acc += beta[s] * wvs[s][hcol];
        sv[hcol] = acc;
    }
    __syncthreads();
    if (tid < NOUT) {
        int o = tid;
        float acc = fcb[o];
        for (int k = 0; k < H2; k++) acc += sv[k] * fcW[(size_t)o * H2 + k];
        int p0 = pairs[nb * 3 + 0];
        int p1 = pairs[nb * 3 + 1];
        int p2 = pairs[nb * 3 + 2];
        out[(((size_t)p0 * NENT + p1) * NENT + p2) * NOUT + o] = acc;
    }
}

// =================== launcher ===================
extern "C" void kernel_launch(void* const* d_in, const int* in_sizes, int n_in,
                              void* d_out, int out_size)
{
    const float* bag       = (const float*)d_in[0];
    const float* W_ih_f    = (const float*)d_in[1];
    const float* W_hh_f    = (const float*)d_in[2];
    const float* b_ih_f    = (const float*)d_in[3];
    const float* b_hh_f    = (const float*)d_in[4];
    const float* W_ih_r    = (const float*)d_in[5];
    const float* W_hh_r    = (const float*)d_in[6];
    const float* b_ih_r    = (const float*)d_in[7];
    const float* b_hh_r    = (const float*)d_in[8];
    const float* W_word    = (const float*)d_in[9];
    const float* b_word    = (const float*)d_in[10];
    const float* proj_word = (const float*)d_in[11];
    const float* W_sent    = (const float*)d_in[12];
    const float* b_sent    = (const float*)d_in[13];
    const float* proj_sent = (const float*)d_in[14];
    const float* fc_W      = (const float*)d_in[15];
    const float* fc_b      = (const float*)d_in[16];
    const int*   pairs     = (const int*)d_in[17];
    float* out = (float*)d_out;

    // 1. input GEMMs (both directions, b_ih fused)
    dim3 gI((G3 + 63) / 64, M_TOT / 128, 2);
    input_gemm<<<gI, 256>>>(bag, W_ih_f, b_ih_f, W_ih_r, b_ih_r);

    // 2. 64 sequential GRU steps (fwd + rev concurrent per launch)
    dim3 gS((HH + 31) / 32, BDIM / 64, 2);
    for (int s = 0; s < TT; s++)
        gru_step<<<gS, 256>>>(W_hh_f, b_hh_f, W_hh_r, b_hh_r, s);

    // 3. word attention scores
    dim3 gW(TT, BDIM / 64);
    word_score<<<gW, 256>>>(W_word, b_word, proj_word);

    // 4. softmax over t + word_vec
    word_attn<<<BDIM, 256>>>();

    // 5. zero output buffer
    int n_out = NDOCS * NENT * NENT * NOUT;
    zero_out<<<(n_out + 255) / 256, 256>>>(out, n_out);

    // 6. sentence attention + FC + scatter
    sent_kernel<<<NBAG, 256>>>(W_sent, b_sent, proj_sent, fc_W, fc_b, pairs, out);
}